// round 6
// baseline (speedup 1.0000x reference)
#include <cuda_runtime.h>
#include <cuda.h>
#include <cstdint>

// Word2Vec negative-sampling loss, R6: TMA tile::gather4 (shared::cta dst).
//   out[b,0]   = softplus(-dot(syn0[inputs[b]], syn1[labels[b]]))
//   out[b,1+n] = softplus( dot(syn0[inputs[b]], syn1[sampled[n,b]]))
// B=16384, H=128 (512B rows), N=5 -> 7 gathered rows/element.
//
// sm_103a supports gather4 only with .shared::cta destination (R5 ptxas
// error named the dst state space, not the feature). One gather4 = 4
// arbitrary rows x 512B = 2KB per request on the TMA bulk path (no L1tex
// MSHR tracking, zero registers in flight).

#define H 128
#define NROW 7             // 1 syn0 row + 6 syn1 rows per element
#define WPB 4              // warps per block
#define QE 4               // elements per quad (per stage)
#define STAGE_BYTES (NROW * QE * H * 4)   // 14336
#define DYN_SMEM (WPB * 2 * STAGE_BYTES)  // 114688

// ---------- PTX helpers ----------
__device__ __forceinline__ uint32_t smem_u32(const void* p) {
    return (uint32_t)__cvta_generic_to_shared(p);
}
__device__ __forceinline__ void mbar_init(uint32_t a, uint32_t cnt) {
    asm volatile("mbarrier.init.shared::cta.b64 [%0], %1;"
                 :: "r"(a), "r"(cnt) : "memory");
}
__device__ __forceinline__ void mbar_expect_tx(uint32_t a, uint32_t bytes) {
    asm volatile("mbarrier.arrive.expect_tx.shared::cta.b64 _, [%0], %1;"
                 :: "r"(a), "r"(bytes) : "memory");
}
__device__ __forceinline__ void mbar_wait(uint32_t a, uint32_t parity) {
    uint32_t done;
    asm volatile(
        "{\n\t.reg .pred p;\n\t"
        "mbarrier.try_wait.parity.acquire.cta.shared::cta.b64 p, [%1], %2;\n\t"
        "selp.b32 %0, 1, 0, p;\n\t}"
        : "=r"(done) : "r"(a), "r"(parity) : "memory");
    if (!done) {
        asm volatile(
            "{\n\t.reg .pred P1;\n\t"
            "WAIT_LOOP_%=:\n\t"
            "mbarrier.try_wait.parity.acquire.cta.shared::cta.b64 P1, [%0], %1, 0x989680;\n\t"
            "@P1 bra.uni WAIT_DONE_%=;\n\t"
            "bra.uni WAIT_LOOP_%=;\n\t"
            "WAIT_DONE_%=:\n\t}"
            :: "r"(a), "r"(parity) : "memory");
    }
}
__device__ __forceinline__ void tma_gather4(
    uint32_t dst, const CUtensorMap* tmap, int col,
    int r0, int r1, int r2, int r3, uint32_t mbar)
{
    asm volatile(
        "cp.async.bulk.tensor.2d.tile::gather4.shared::cta.global"
        ".mbarrier::complete_tx::bytes"
        " [%0], [%1, {%2, %3, %4, %5, %6}], [%7];"
        :: "r"(dst), "l"(tmap), "r"(col),
           "r"(r0), "r"(r1), "r"(r2), "r"(r3), "r"(mbar)
        : "memory");
}
__device__ __forceinline__ float softplus_f(float x) {
    return fmaxf(x, 0.0f) + log1pf(__expf(-fabsf(x)));
}

// ---------- TMA gather4 kernel ----------
__global__ __launch_bounds__(32 * WPB) void w2v_tma_kernel(
    const int* __restrict__ inputs,
    const int* __restrict__ labels,
    const int* __restrict__ sampled,    // [N, B]
    float* __restrict__ out,            // [B, 6]
    int B,
    const __grid_constant__ CUtensorMap tm0,   // syn0 [V, 128] f32
    const __grid_constant__ CUtensorMap tm1)   // syn1 [V, 128] f32
{
    extern __shared__ __align__(1024) char smem[];
    __shared__ alignas(8) uint64_t mbar_s[WPB][2];

    const int w    = threadIdx.x >> 5;
    const int lane = threadIdx.x & 31;
    const int grp  = lane >> 3;          // element within quad (0..3)
    const int sub  = lane & 7;           // lane within 8-group
    const int gwarp = blockIdx.x * WPB + w;
    const int W     = gridDim.x * WPB;   // total warps
    const int NQ    = B >> 2;            // quads

    if (lane == 0) {
        mbar_init(smem_u32(&mbar_s[w][0]), 1);
        mbar_init(smem_u32(&mbar_s[w][1]), 1);
    }
    asm volatile("fence.proxy.async.shared::cta;" ::: "memory");
    __syncthreads();

    if (gwarp >= NQ) return;

    auto issue = [&](int st, int q) {
        if (lane != 0) return;
        const int qb = q << 2;
        uint32_t mb  = smem_u32(&mbar_s[w][st]);
        uint32_t dst = smem_u32(smem + (w * 2 + st) * STAGE_BYTES);
        mbar_expect_tx(mb, STAGE_BYTES);

        int4 i0 = *reinterpret_cast<const int4*>(inputs + qb);
        tma_gather4(dst, &tm0, 0, i0.x, i0.y, i0.z, i0.w, mb);
        int4 l0 = *reinterpret_cast<const int4*>(labels + qb);
        tma_gather4(dst + 2048, &tm1, 0, l0.x, l0.y, l0.z, l0.w, mb);
#pragma unroll
        for (int n = 0; n < 5; n++) {
            int4 s = *reinterpret_cast<const int4*>(sampled + n * B + qb);
            tma_gather4(dst + (2 + n) * 2048, &tm1, 0, s.x, s.y, s.z, s.w, mb);
        }
    };

    // prologue: fill both stages
    issue(0, gwarp);
    if (gwarp + W < NQ) issue(1, gwarp + W);

    int k = 0;
    for (int q = gwarp; q < NQ; q += W, k++) {
        const int st = k & 1;
        mbar_wait(smem_u32(&mbar_s[w][st]), (k >> 1) & 1);

        const float4* s4 = reinterpret_cast<const float4*>(
            smem + (w * 2 + st) * STAGE_BYTES);
        // gather4 chunk r: [4 rows][512B]; element grp's row r at
        // float4 offset r*128 + grp*32. Lane reads float4 sub+8c -> the
        // 8 lanes of a group cover one contiguous 128B phase (conflict-free).
        float4 u[4];
#pragma unroll
        for (int c = 0; c < 4; c++) u[c] = s4[grp * 32 + sub + 8 * c];

        float dot[6];
#pragma unroll
        for (int t = 0; t < 6; t++) {
            const float4* v4 = s4 + (1 + t) * 128 + grp * 32;
            float d = 0.0f;
#pragma unroll
            for (int c = 0; c < 4; c++) {
                float4 v = v4[sub + 8 * c];
                d += u[c].x * v.x + u[c].y * v.y + u[c].z * v.z + u[c].w * v.w;
            }
#pragma unroll
            for (int o = 4; o > 0; o >>= 1)      // reduce within 8 lanes
                d += __shfl_xor_sync(0xffffffffu, d, o);
            dot[t] = d;
        }

        if (sub < 6) {
            int b = (q << 2) + grp;
            float x = (sub == 0) ? -dot[0]
                    : (sub == 1) ? dot[1]
                    : (sub == 2) ? dot[2]
                    : (sub == 3) ? dot[3]
                    : (sub == 4) ? dot[4] : dot[5];
            out[b * 6 + sub] = softplus_f(x);
        }

        if (q + 2 * W < NQ) issue(st, q + 2 * W);   // refill drained stage
    }
}

// ---------- fallback: R4 cp.async kernel (proven, 12.4us) ----------
#define FWPB 3
__device__ __forceinline__ void cpa16(uint32_t dst_smem, const void* src) {
    asm volatile("cp.async.cg.shared.global [%0], [%1], 16;"
                 :: "r"(dst_smem), "l"(src) : "memory");
}
__device__ __forceinline__ void cpa_commit() {
    asm volatile("cp.async.commit_group;" ::: "memory");
}
template <int N>
__device__ __forceinline__ void cpa_wait() {
    asm volatile("cp.async.wait_group %0;" :: "n"(N) : "memory");
}

__global__ __launch_bounds__(32 * FWPB) void w2v_fb_kernel(
    const int* __restrict__ inputs, const int* __restrict__ labels,
    const int* __restrict__ sampled, const float* __restrict__ syn0,
    const float* __restrict__ syn1, float* __restrict__ out, int B)
{
    __shared__ float4 buf[FWPB][2][NROW][2][32];
    const int w = threadIdx.x >> 5, lane = threadIdx.x & 31;
    const int half = lane >> 4, sub = lane & 15;
    const int gwarp = blockIdx.x * FWPB + w;
    const int W = gridDim.x * FWPB;
    const int NP = (B + 1) >> 1;
    if (gwarp >= NP) return;

    auto ldidx = [&](int p, int* t) {
        int b = 2 * p + half; if (b >= B) b = B - 1;
        t[0] = __ldg(inputs + b); t[1] = __ldg(labels + b);
#pragma unroll
        for (int n = 0; n < 5; n++) t[2 + n] = __ldg(sampled + n * B + b);
    };
    auto issue = [&](int st, const int* t) {
#pragma unroll
        for (int r = 0; r < NROW; r++) {
            const float* base = (r == 0 ? syn0 : syn1)
                              + ((size_t)(unsigned)t[r] << 7) + sub * 4;
#pragma unroll
            for (int c = 0; c < 2; c++)
                cpa16((uint32_t)__cvta_generic_to_shared(&buf[w][st][r][c][lane]),
                      base + c * 64);
        }
        cpa_commit();
    };

    int idx[NROW];
    ldidx(gwarp, idx); issue(0, idx);
    if (gwarp + W < NP) { ldidx(gwarp + W, idx); issue(1, idx); }

    int pn = gwarp + 2 * W, k = 0;
    for (int p = gwarp; p < NP; p += W, k++) {
        int idxn[NROW];
        const bool hasn = (pn < NP);
        if (hasn) ldidx(pn, idxn);
        if (p + W < NP) cpa_wait<1>(); else cpa_wait<0>();
        const int st = k & 1;
        const float4 u0 = buf[w][st][0][0][lane];
        const float4 u1 = buf[w][st][0][1][lane];
        float dot[6];
#pragma unroll
        for (int t = 0; t < 6; t++) {
            float4 v0 = buf[w][st][1 + t][0][lane];
            float4 v1 = buf[w][st][1 + t][1][lane];
            float d = u0.x * v0.x + u0.y * v0.y + u0.z * v0.z + u0.w * v0.w
                    + u1.x * v1.x + u1.y * v1.y + u1.z * v1.z + u1.w * v1.w;
#pragma unroll
            for (int o = 8; o > 0; o >>= 1)
                d += __shfl_xor_sync(0xffffffffu, d, o);
            dot[t] = d;
        }
        if (sub == 0) {
            int b = 2 * p + half;
            if (b < B) {
                out[b * 6 + 0] = softplus_f(-dot[0]);
#pragma unroll
                for (int t = 1; t < 6; t++) out[b * 6 + t] = softplus_f(dot[t]);
            }
        }
        if (hasn) issue(st, idxn);
        pn += W;
    }
}

// ---------- host ----------
typedef CUresult (*EncodeTiledFn)(
    CUtensorMap*, CUtensorMapDataType, cuuint32_t, void*,
    const cuuint64_t*, const cuuint64_t*, const cuuint32_t*, const cuuint32_t*,
    CUtensorMapInterleave, CUtensorMapSwizzle, CUtensorMapL2promotion,
    CUtensorMapFloatOOBfill);

static bool encode_map(EncodeTiledFn fn, CUtensorMap* tm, void* base,
                       unsigned long long nrows)
{
    cuuint64_t dims[2]    = {H, nrows};
    cuuint64_t strides[1] = {H * sizeof(float)};
    cuuint32_t box[2]     = {H, 1};
    cuuint32_t estr[2]    = {1, 1};
    return fn(tm, CU_TENSOR_MAP_DATA_TYPE_FLOAT32, 2, base,
              dims, strides, box, estr,
              CU_TENSOR_MAP_INTERLEAVE_NONE, CU_TENSOR_MAP_SWIZZLE_NONE,
              CU_TENSOR_MAP_L2_PROMOTION_L2_128B,
              CU_TENSOR_MAP_FLOAT_OOB_FILL_NONE) == CUDA_SUCCESS;
}

extern "C" void kernel_launch(void* const* d_in, const int* in_sizes, int n_in,
                              void* d_out, int out_size)
{
    const int*   inputs  = (const int*)d_in[0];
    const int*   labels  = (const int*)d_in[1];
    const int*   sampled = (const int*)d_in[2];
    const float* syn0    = (const float*)d_in[3];
    const float* syn1    = (const float*)d_in[4];
    float*       out     = (float*)d_out;
    const int B = in_sizes[0];

    bool use_tma = (B % 4 == 0);
    CUtensorMap tm0, tm1;
    if (use_tma) {
        EncodeTiledFn fn = nullptr;
        cudaDriverEntryPointQueryResult st;
#if CUDART_VERSION >= 12050
        if (cudaGetDriverEntryPointByVersion("cuTensorMapEncodeTiled",
                (void**)&fn, 12050, cudaEnableDefault, &st) != cudaSuccess)
            fn = nullptr;
#else
        if (cudaGetDriverEntryPoint("cuTensorMapEncodeTiled",
                (void**)&fn, cudaEnableDefault, &st) != cudaSuccess)
            fn = nullptr;
#endif
        if (!fn
            || !encode_map(fn, &tm0, (void*)syn0, (unsigned long long)(in_sizes[3] / H))
            || !encode_map(fn, &tm1, (void*)syn1, (unsigned long long)(in_sizes[4] / H)))
            use_tma = false;
    }

    if (use_tma) {
        cudaFuncSetAttribute(w2v_tma_kernel,
                             cudaFuncAttributeMaxDynamicSharedMemorySize, DYN_SMEM);
        const int NQ = B >> 2;                         // 4096 quads
        int blocks = 2 * 148;                          // 2 blocks/SM, 1 wave
        int maxb = (NQ + WPB - 1) / WPB;
        if (blocks > maxb) blocks = maxb;
        w2v_tma_kernel<<<blocks, 32 * WPB, DYN_SMEM>>>(
            inputs, labels, sampled, out, B, tm0, tm1);
    } else {
        const int NP = (B + 1) / 2;
        int warps  = (NP + 3) / 4;
        int blocks = (warps + FWPB - 1) / FWPB;
        w2v_fb_kernel<<<blocks, 32 * FWPB>>>(
            inputs, labels, sampled, syn0, syn1, out, B);
    }
}